// round 12
// baseline (speedup 1.0000x reference)
#include <cuda_runtime.h>
#include <cuda_bf16.h>
#include <cstdint>

#define EN 160000      // edges = N*K
#define NN 10000       // nodes

// ---------------- static device scratch -----------------------------------------------------
__device__ __align__(16) uint4 g_Bf[12 * 1024];   // W2 bf16 packed {hi0,hi1,lo0,lo1} [chunk][kt][nt][lane]
__device__ __align__(16) uint4 g_W1f[512];        // W1 bf16 packed [kt2(2)][nt(8)][lane]

// ---------------- helpers --------------------------------------------------------------------
__device__ __forceinline__ uint32_t smem_u32(const void* p) {
    uint32_t a;
    asm("{ .reg .u64 t; cvta.to.shared.u64 t, %1; cvt.u32.u64 %0, t; }" : "=r"(a) : "l"(p));
    return a;
}
__device__ __forceinline__ void mma_bf16(float* c, const uint32_t* a, const uint32_t* b) {
    asm volatile("mma.sync.aligned.m16n8k16.row.col.f32.bf16.bf16.f32 "
        "{%0,%1,%2,%3}, {%4,%5,%6,%7}, {%8,%9}, {%0,%1,%2,%3};"
        : "+f"(c[0]), "+f"(c[1]), "+f"(c[2]), "+f"(c[3])
        : "r"(a[0]), "r"(a[1]), "r"(a[2]), "r"(a[3]), "r"(b[0]), "r"(b[1]));
}
__device__ __forceinline__ void cpa16(uint32_t dst, const void* src) {
    asm volatile("cp.async.cg.shared.global [%0], [%1], 16;" :: "r"(dst), "l"(src));
}
#define CP_COMMIT() asm volatile("cp.async.commit_group;" ::: "memory")
#define CP_WAIT(n)  asm volatile("cp.async.wait_group %0;" :: "n"(n) : "memory")

__device__ __forceinline__ void split2bf(float a, float b, uint32_t& h, uint32_t& l) {
    __nv_bfloat16 ah = __float2bfloat16(a), bh = __float2bfloat16(b);
    __nv_bfloat16 al = __float2bfloat16(a - __bfloat162float(ah));
    __nv_bfloat16 bl = __float2bfloat16(b - __bfloat162float(bh));
    h = (uint32_t)__bfloat16_as_ushort(ah) | ((uint32_t)__bfloat16_as_ushort(bh) << 16);
    l = (uint32_t)__bfloat16_as_ushort(al) | ((uint32_t)__bfloat16_as_ushort(bl) << 16);
}

// ---------------- Kernel P: pack W2 (12 blocks) and W1 (block 12), bf16 hi/lo ----------------
__global__ void k_prep(const float* __restrict__ W2, const float* __restrict__ W1) {
    int bid = blockIdx.x, tid = threadIdx.x;
    if (bid < 12) {
        int c = bid;
        for (int idx = tid; idx < 1024; idx += 128) {
            int kt = idx >> 8, nt = (idx >> 5) & 7, l = idx & 31;
            int row = c * 64 + nt * 8 + (l >> 2);
            int j0 = kt * 16 + (l & 3) * 2;
            const float* wr = W2 + (size_t)row * 64;
            uint4 v;
            split2bf(__ldg(&wr[j0]),     __ldg(&wr[j0 + 1]), v.x, v.z);
            split2bf(__ldg(&wr[j0 + 8]), __ldg(&wr[j0 + 9]), v.y, v.w);
            g_Bf[c * 1024 + idx] = v;
        }
    } else {
        for (int idx = tid; idx < 512; idx += 128) {
            int kt = idx >> 8, nt = (idx >> 5) & 7, l = idx & 31;
            int j = nt * 8 + (l >> 2);
            int c0 = kt * 16 + (l & 3) * 2;
            const float* wr = W1 + (size_t)j * 32;
            uint4 v;
            split2bf(__ldg(&wr[c0]),     __ldg(&wr[c0 + 1]), v.x, v.z);
            split2bf(__ldg(&wr[c0 + 8]), __ldg(&wr[c0 + 9]), v.y, v.w);
            g_W1f[idx] = v;
        }
    }
}

// ---------------- Kernel A: MLP(bf16x3) + GEMM(bf16x3) + epilogue + in-CTA attention ---------
// CTA = 128 edges = 8 nodes; TARGET 4 CTAs/SM (16 warps) via <=128 regs:
//  - acc[2][2][4] (chunk-quarter granularity), b-frags 2 at a time
//  - awl[mt=1] lives in per-warp smem (written in MLP, per-lane LDS.128 reload)
// Barrier-free main loop (B via __ldg, warps free-run).
#define S_KQV  0u              // 16 planes x 128 x 16B = 32768
#define S_TMP  0u              //   tmp 8K aliases planes 0-3 (dead before plane writes)
#define S_EF   0u              //   prologue scratch: 128 x 144B = 18432 (dead before tmp)
#define S_W1F  18432u          //   prologue scratch: 8192 (dead before v-plane writes)
#define S_B1   26624u          //   prologue scratch: 256
#define S_QN   32768u          // 1024
#define S_B2   33792u          // 3072  ..36864
#define S_BAS  36864u          // 4096  ..40960
#define S_AL   40960u          // Al(mt=1) frags: [wid][kt][lane] uint4 = 8192 ..49152
#define SMEM_SZ (49152u + 1024u)

__global__ void __launch_bounds__(128, 4) k_main(const float* __restrict__ b2,
                                                 const float* __restrict__ basis2,
                                                 const float* __restrict__ basis1,
                                                 const float* __restrict__ f,
                                                 const int* __restrict__ nbr,
                                                 const float* __restrict__ ef,
                                                 const float* __restrict__ b1,
                                                 float* __restrict__ out) {
    extern __shared__ unsigned char smraw[];
    uint32_t base = (smem_u32(smraw) + 1023u) & ~1023u;
    unsigned char* sm = smraw + (base - smem_u32(smraw));
    const float* sB2f = (const float*)(sm + S_B2);
    int tid = threadIdx.x, blk = blockIdx.x;
    int wid = tid >> 5, lane = tid & 31;
    int q = lane & 3;

    // ---- prologue: ef tile + W1 frags + b1 + b2 + basis2 ----
    {
        for (int r = tid; r < 1024; r += 128) {
            int row = r >> 3, seg = r & 7;
            cpa16(base + S_EF + (uint32_t)row * 144u + (uint32_t)seg * 16u,
                  ef + ((size_t)(blk * 128 + row)) * 32 + seg * 4);
        }
        const uint4* wf = (const uint4*)g_W1f;
        for (int r = tid; r < 512; r += 128) cpa16(base + S_W1F + r * 16, wf + r);
        const uint4* g1 = (const uint4*)b1;
        for (int r = tid; r < 16; r += 128) cpa16(base + S_B1 + r * 16, g1 + r);
        const uint4* g2 = (const uint4*)b2;
        for (int r = tid; r < 192; r += 128) cpa16(base + S_B2 + r * 16, g2 + r);
        const uint4* gb = (const uint4*)(basis2 + (size_t)blk * 1024);
        for (int r = tid; r < 256; r += 128) cpa16(base + S_BAS + r * 16, gb + r);
        CP_COMMIT();
    }
    CP_WAIT(0);
    __syncthreads();

    // ---- MLP (bf16x3 tensor): h = relu(ef @ W1^T + b1) -> A frags (hi regs; lo: mt0 regs,
    //      mt1 -> per-warp smem slab) ----
    uint32_t awh[2][4][4];   // hi frags [mt][kt][r]
    uint32_t awl0[4][4];     // lo frags mt=0 only [kt][r]
    {
        uint32_t efh[2][2][4], efl[2][2][4];
        const float* sEF = (const float*)(sm + S_EF);
#pragma unroll
        for (int mt = 0; mt < 2; mt++)
#pragma unroll
            for (int kt = 0; kt < 2; kt++) {
                int r0 = wid * 32 + mt * 16 + (lane >> 2);
                int c0 = kt * 16 + 2 * q;
                float2 v0 = *(const float2*)&sEF[r0 * 36 + c0];
                float2 v1 = *(const float2*)&sEF[(r0 + 8) * 36 + c0];
                float2 v2 = *(const float2*)&sEF[r0 * 36 + c0 + 8];
                float2 v3 = *(const float2*)&sEF[(r0 + 8) * 36 + c0 + 8];
                split2bf(v0.x, v0.y, efh[mt][kt][0], efl[mt][kt][0]);
                split2bf(v1.x, v1.y, efh[mt][kt][1], efl[mt][kt][1]);
                split2bf(v2.x, v2.y, efh[mt][kt][2], efl[mt][kt][2]);
                split2bf(v3.x, v3.y, efh[mt][kt][3], efl[mt][kt][3]);
            }
        const float* sb1 = (const float*)(sm + S_B1);
#pragma unroll
        for (int nth = 0; nth < 2; nth++) {
            float hc[2][4][4];
#pragma unroll
            for (int mt = 0; mt < 2; mt++)
#pragma unroll
                for (int n4 = 0; n4 < 4; n4++)
#pragma unroll
                    for (int x = 0; x < 4; x++) hc[mt][n4][x] = 0.0f;
#pragma unroll
            for (int kt2 = 0; kt2 < 2; kt2++) {
                uint4 w[4];
#pragma unroll
                for (int n4 = 0; n4 < 4; n4++)
                    w[n4] = *(const uint4*)(sm + S_W1F +
                        (uint32_t)(((kt2 * 8 + nth * 4 + n4) * 32 + lane) * 16));
#pragma unroll
                for (int ps = 0; ps < 3; ps++)
#pragma unroll
                    for (int n4 = 0; n4 < 4; n4++) {
                        const uint32_t* bp = (ps == 1) ? &w[n4].z : &w[n4].x;
#pragma unroll
                        for (int mt = 0; mt < 2; mt++)
                            mma_bf16(hc[mt][n4], (ps == 2) ? efl[mt][kt2] : efh[mt][kt2], bp);
                    }
            }
#pragma unroll
            for (int n4 = 0; n4 < 4; n4++) {
                int nt = nth * 4 + n4;
                float ba = sb1[nt * 8 + 2 * q], bb = sb1[nt * 8 + 2 * q + 1];
                int ktA = nt >> 1, rg = (nt & 1) * 2;
#pragma unroll
                for (int mt = 0; mt < 2; mt++) {
                    float x0 = fmaxf(hc[mt][n4][0] + ba, 0.f);
                    float x1 = fmaxf(hc[mt][n4][1] + bb, 0.f);
                    float x2 = fmaxf(hc[mt][n4][2] + ba, 0.f);
                    float x3 = fmaxf(hc[mt][n4][3] + bb, 0.f);
                    uint32_t h01, l01, h23, l23;
                    split2bf(x0, x1, h01, l01);
                    split2bf(x2, x3, h23, l23);
                    awh[mt][ktA][rg]     = h01;
                    awh[mt][ktA][rg + 1] = h23;
                    if (mt == 0) {
                        awl0[ktA][rg]     = l01;
                        awl0[ktA][rg + 1] = l23;
                    } else {
                        // per-lane slab: no cross-lane sharing, no sync needed
                        uint32_t off = S_AL + (uint32_t)(((wid * 4 + ktA) * 32 + lane) * 16)
                                     + (uint32_t)rg * 4u;
                        asm volatile("st.shared.v2.b32 [%0], {%1, %2};"
                                     :: "r"(base + off), "r"(l01), "r"(l23) : "memory");
                    }
                }
            }
        }
    }
    __syncthreads();           // EF/W1F/B1 scratch dead for all warps

    // ---- tmp: tmp[e, m*2+l] = sum_d f[src,m,d]*basis1[e,d,l] ----
    {
        int e = blk * 128 + tid;
        int src = __ldg(&nbr[e]);
        const float4* fp = (const float4*)(f + (size_t)src * 32);
        float fr[8][4];
#pragma unroll
        for (int m = 0; m < 8; m++) {
            float4 v = __ldg(&fp[m]);
            fr[m][0] = v.x; fr[m][1] = v.y; fr[m][2] = v.z; fr[m][3] = v.w;
        }
        float4 b0 = __ldg((const float4*)(basis1 + (size_t)e * 8));
        float4 b1v = __ldg((const float4*)(basis1 + (size_t)e * 8 + 4));
        float bd[4][2] = {{b0.x, b0.y}, {b0.z, b0.w}, {b1v.x, b1v.y}, {b1v.z, b1v.w}};
        float* dst = (float*)(sm + S_TMP);
#pragma unroll
        for (int m = 0; m < 8; m++)
#pragma unroll
            for (int l = 0; l < 2; l++) {
                float a = fr[m][0] * bd[0][l];
                a = fmaf(fr[m][1], bd[1][l], a);
                a = fmaf(fr[m][2], bd[2][l], a);
                a = fmaf(fr[m][3], bd[3][l], a);
                dst[(m * 2 + l) * 128 + tid] = a;
            }
    }
    __syncthreads();           // tmp visible to all warps

    float tr[4][4];
    {
        const float* sTMPf = (const float*)(sm + S_TMP);
#pragma unroll
        for (int rid = 0; rid < 4; rid++) {
            int row = wid * 32 + (lane >> 2) + rid * 8;
#pragma unroll
            for (int s = 0; s < 4; s++) {
                int i = (s >> 1) * 8 + 2 * q + (s & 1);
                tr[rid][s] = sTMPf[i * 128 + row];
            }
        }
    }
    __syncthreads();           // ALL warps' tr loaded before plane writes clobber tmp bytes

    float acc[2][2][4];        // [mt][n4local][4] — quarter-size accumulator
#pragma unroll
    for (int mt = 0; mt < 2; mt++)
#pragma unroll
        for (int n4 = 0; n4 < 2; n4++)
#pragma unroll
            for (int x = 0; x < 4; x++) acc[mt][n4][x] = 0.0f;

    // ==== free-running main loop: bf16x3, quarter-granular MMA+epilogue, no barriers ====
    for (int c = 0; c < 12; c++) {
        const uint4* bc = g_Bf + (size_t)c * 1024;
#pragma unroll
        for (int ntg = 0; ntg < 2; ntg++) {
            float p[4][2];
#pragma unroll
            for (int rid = 0; rid < 4; rid++) { p[rid][0] = 0.f; p[rid][1] = 0.f; }

#pragma unroll
            for (int qt = 0; qt < 2; qt++) {
#pragma unroll
                for (int kt = 0; kt < 4; kt++) {
                    uint4 b0 = __ldg(&bc[(size_t)((kt * 8 + ntg * 4 + qt * 2) * 32 + lane)]);
                    uint4 b1 = __ldg(&bc[(size_t)((kt * 8 + ntg * 4 + qt * 2 + 1) * 32 + lane)]);
                    uint4 al1;
                    asm volatile("ld.shared.v4.b32 {%0,%1,%2,%3}, [%4];"
                        : "=r"(al1.x), "=r"(al1.y), "=r"(al1.z), "=r"(al1.w)
                        : "r"(base + S_AL + (uint32_t)(((wid * 4 + kt) * 32 + lane) * 16)));
                    // n4local 0 (b0)
                    mma_bf16(acc[0][0], awh[0][kt], &b0.x);
                    mma_bf16(acc[0][0], awh[0][kt], &b0.z);
                    mma_bf16(acc[0][0], awl0[kt],   &b0.x);
                    mma_bf16(acc[1][0], awh[1][kt], &b0.x);
                    mma_bf16(acc[1][0], awh[1][kt], &b0.z);
                    mma_bf16(acc[1][0], &al1.x,     &b0.x);
                    // n4local 1 (b1)
                    mma_bf16(acc[0][1], awh[0][kt], &b1.x);
                    mma_bf16(acc[0][1], awh[0][kt], &b1.z);
                    mma_bf16(acc[0][1], awl0[kt],   &b1.x);
                    mma_bf16(acc[1][1], awh[1][kt], &b1.x);
                    mma_bf16(acc[1][1], awh[1][kt], &b1.z);
                    mma_bf16(acc[1][1], &al1.x,     &b1.x);
                }
                // ---- quarter epilogue: fold (acc + b2)*tmp into p[rid][qt] ----
#pragma unroll
                for (int mt = 0; mt < 2; mt++)
#pragma unroll
                    for (int n4l = 0; n4l < 2; n4l++) {
                        int s0 = n4l * 2;
                        float2 bb = *(const float2*)&sB2f[c * 64 +
                                     (ntg * 4 + qt * 2 + n4l) * 8 + q * 2];
#pragma unroll
                        for (int h = 0; h < 2; h++) {
                            int rid = mt * 2 + h;
                            p[rid][qt] = fmaf(acc[mt][n4l][h * 2] + bb.x, tr[rid][s0],
                                         fmaf(acc[mt][n4l][h * 2 + 1] + bb.y, tr[rid][s0 + 1],
                                              p[rid][qt]));
                            acc[mt][n4l][h * 2] = 0.0f;
                            acc[mt][n4l][h * 2 + 1] = 0.0f;
                        }
                    }
            }

#pragma unroll
            for (int rid = 0; rid < 4; rid++)
#pragma unroll
                for (int o2 = 0; o2 < 2; o2++) {
                    p[rid][o2] += __shfl_xor_sync(0xffffffffu, p[rid][o2], 1);
                    p[rid][o2] += __shfl_xor_sync(0xffffffffu, p[rid][o2], 2);
                }

            if (c < 4 || c >= 8) {
                if (q == 0) {
                    int plane = ((c < 4) ? (c * 2) : ((c - 8) * 2 + 8)) + ntg;
#pragma unroll
                    for (int rid = 0; rid < 4; rid++) {
                        int el = wid * 32 + (lane >> 2) + rid * 8;
                        float4 p0 = *(const float4*)(sm + S_BAS + el * 32);
                        float4 p1 = *(const float4*)(sm + S_BAS + el * 32 + 16);
                        float a0 = p[rid][0], a1 = p[rid][1];
                        float4 o4;
                        o4.x = fmaf(a0, p0.x, a1 * p1.x);
                        o4.y = fmaf(a0, p0.y, a1 * p1.y);
                        o4.z = fmaf(a0, p0.z, a1 * p1.z);
                        o4.w = fmaf(a0, p0.w, a1 * p1.w);
                        *(float4*)(sm + S_KQV + (size_t)plane * 2048 + el * 16) = o4;
                    }
                }
            } else {
                int qp = (c - 4) * 2 + ntg;
                float4 an[2];
                an[0] = make_float4(0.f, 0.f, 0.f, 0.f);
                an[1] = make_float4(0.f, 0.f, 0.f, 0.f);
#pragma unroll
                for (int rid = 0; rid < 4; rid++) {
                    int el = wid * 32 + (lane >> 2) + rid * 8;
                    float4 p0 = *(const float4*)(sm + S_BAS + el * 32);
                    float4 p1 = *(const float4*)(sm + S_BAS + el * 32 + 16);
                    int nn = rid >> 1;
                    float a0 = p[rid][0], a1 = p[rid][1];
                    an[nn].x = fmaf(a0, p0.x, fmaf(a1, p1.x, an[nn].x));
                    an[nn].y = fmaf(a0, p0.y, fmaf(a1, p1.y, an[nn].y));
                    an[nn].z = fmaf(a0, p0.z, fmaf(a1, p1.z, an[nn].z));
                    an[nn].w = fmaf(a0, p0.w, fmaf(a1, p1.w, an[nn].w));
                }
#pragma unroll
                for (int nn = 0; nn < 2; nn++)
#pragma unroll
                    for (int d = 4; d <= 16; d <<= 1) {
                        an[nn].x += __shfl_xor_sync(0xffffffffu, an[nn].x, d);
                        an[nn].y += __shfl_xor_sync(0xffffffffu, an[nn].y, d);
                        an[nn].z += __shfl_xor_sync(0xffffffffu, an[nn].z, d);
                        an[nn].w += __shfl_xor_sync(0xffffffffu, an[nn].w, d);
                    }
                if (lane == 0) {
                    *(float4*)(sm + S_QN + (size_t)((wid * 2 + 0) * 8 + qp) * 16) = an[0];
                    *(float4*)(sm + S_QN + (size_t)((wid * 2 + 1) * 8 + qp) * 16) = an[1];
                }
            }
        }
    }

    // ---- in-CTA attention: 8 nodes, 16 lanes per node ----
    __syncthreads();
    {
        int k16 = lane & 15, nh = lane >> 4;
        int nl = wid * 2 + nh;
        int n = blk * 8 + nl;
        int el = nl * 16 + k16;
        float s[4] = {0.f, 0.f, 0.f, 0.f};
#pragma unroll
        for (int pp = 0; pp < 8; pp++) {
            float4 kv = *(const float4*)(sm + S_KQV + (size_t)pp * 2048 + el * 16);
            float4 qv = *(const float4*)(sm + S_QN + (size_t)(nl * 8 + pp) * 16);
            s[pp >> 1] = fmaf(kv.x, qv.x, fmaf(kv.y, qv.y,
                         fmaf(kv.z, qv.z, fmaf(kv.w, qv.w, s[pp >> 1]))));
        }
        const float scale = 0.35355339059327373f * 0.0625f;  // 8^-0.5 * 1/16 (q mean)
#pragma unroll
        for (int h = 0; h < 4; h++) {
            s[h] *= scale;
            float m = s[h];
#pragma unroll
            for (int d = 1; d < 16; d <<= 1)
                m = fmaxf(m, __shfl_xor_sync(0xffffffffu, m, d));
            float w = __expf(s[h] - m);
            float z = w;
#pragma unroll
            for (int d = 1; d < 16; d <<= 1)
                z += __shfl_xor_sync(0xffffffffu, z, d);
            s[h] = w / z;
        }
#pragma unroll
        for (int pp = 0; pp < 8; pp++) {
            float4 vv = *(const float4*)(sm + S_KQV + (size_t)(8 + pp) * 2048 + el * 16);
            float w = s[pp >> 1];
            float4 o4 = make_float4(w * vv.x, w * vv.y, w * vv.z, w * vv.w);
#pragma unroll
            for (int d = 1; d < 16; d <<= 1) {
                o4.x += __shfl_xor_sync(0xffffffffu, o4.x, d);
                o4.y += __shfl_xor_sync(0xffffffffu, o4.y, d);
                o4.z += __shfl_xor_sync(0xffffffffu, o4.z, d);
                o4.w += __shfl_xor_sync(0xffffffffu, o4.w, d);
            }
            if (k16 == 0)
                *(float4*)(out + (size_t)n * 32 + pp * 4) = o4;
        }
    }
}

extern "C" void kernel_launch(void* const* d_in, const int* in_sizes, int n_in,
                              void* d_out, int out_size) {
    const float* basis1 = (const float*)d_in[0];
    const float* basis2 = (const float*)d_in[1];
    const float* ef     = (const float*)d_in[2];
    const float* f      = (const float*)d_in[3];
    const float* W1     = (const float*)d_in[4];
    const float* b1     = (const float*)d_in[5];
    const float* W2     = (const float*)d_in[6];
    const float* b2     = (const float*)d_in[7];
    const int*   nbr    = (const int*)d_in[8];
    float* out = (float*)d_out;

    cudaFuncSetAttribute(k_main, cudaFuncAttributeMaxDynamicSharedMemorySize, SMEM_SZ);

    k_prep<<<13, 128>>>(W2, W1);
    k_main<<<EN / 128, 128, SMEM_SZ>>>(b2, basis2, basis1, f, nbr, ef, b1, out);
}

// round 13
// speedup vs baseline: 1.0440x; 1.0440x over previous
#include <cuda_runtime.h>
#include <cuda_bf16.h>
#include <cstdint>

#define EN 160000      // edges = N*K
#define NN 10000       // nodes

// ---------------- static device scratch -----------------------------------------------------
__device__ __align__(16) uint4 g_Bf[12 * 1024];   // W2 bf16 packed {hi0,hi1,lo0,lo1} [chunk][kt][nt][lane]
__device__ __align__(16) uint4 g_W1f[512];        // W1 bf16 packed [kt2(2)][nt(8)][lane]

// ---------------- helpers --------------------------------------------------------------------
__device__ __forceinline__ uint32_t smem_u32(const void* p) {
    uint32_t a;
    asm("{ .reg .u64 t; cvta.to.shared.u64 t, %1; cvt.u32.u64 %0, t; }" : "=r"(a) : "l"(p));
    return a;
}
__device__ __forceinline__ void mma_bf16(float* c, const uint32_t* a, const uint32_t* b) {
    asm volatile("mma.sync.aligned.m16n8k16.row.col.f32.bf16.bf16.f32 "
        "{%0,%1,%2,%3}, {%4,%5,%6,%7}, {%8,%9}, {%0,%1,%2,%3};"
        : "+f"(c[0]), "+f"(c[1]), "+f"(c[2]), "+f"(c[3])
        : "r"(a[0]), "r"(a[1]), "r"(a[2]), "r"(a[3]), "r"(b[0]), "r"(b[1]));
}
__device__ __forceinline__ void cpa16(uint32_t dst, const void* src) {
    asm volatile("cp.async.cg.shared.global [%0], [%1], 16;" :: "r"(dst), "l"(src));
}
#define CP_COMMIT() asm volatile("cp.async.commit_group;" ::: "memory")
#define CP_WAIT(n)  asm volatile("cp.async.wait_group %0;" :: "n"(n) : "memory")

__device__ __forceinline__ void split2bf(float a, float b, uint32_t& h, uint32_t& l) {
    __nv_bfloat16 ah = __float2bfloat16(a), bh = __float2bfloat16(b);
    __nv_bfloat16 al = __float2bfloat16(a - __bfloat162float(ah));
    __nv_bfloat16 bl = __float2bfloat16(b - __bfloat162float(bh));
    h = (uint32_t)__bfloat16_as_ushort(ah) | ((uint32_t)__bfloat16_as_ushort(bh) << 16);
    l = (uint32_t)__bfloat16_as_ushort(al) | ((uint32_t)__bfloat16_as_ushort(bl) << 16);
}

// ---------------- Kernel P: pack W2 (12 blocks) and W1 (block 12), bf16 hi/lo ----------------
__global__ void k_prep(const float* __restrict__ W2, const float* __restrict__ W1) {
    int bid = blockIdx.x, tid = threadIdx.x;
    if (bid < 12) {
        int c = bid;
        for (int idx = tid; idx < 1024; idx += 128) {
            int kt = idx >> 8, nt = (idx >> 5) & 7, l = idx & 31;
            int row = c * 64 + nt * 8 + (l >> 2);
            int j0 = kt * 16 + (l & 3) * 2;
            const float* wr = W2 + (size_t)row * 64;
            uint4 v;
            split2bf(__ldg(&wr[j0]),     __ldg(&wr[j0 + 1]), v.x, v.z);
            split2bf(__ldg(&wr[j0 + 8]), __ldg(&wr[j0 + 9]), v.y, v.w);
            g_Bf[c * 1024 + idx] = v;
        }
    } else {
        for (int idx = tid; idx < 512; idx += 128) {
            int kt = idx >> 8, nt = (idx >> 5) & 7, l = idx & 31;
            int j = nt * 8 + (l >> 2);
            int c0 = kt * 16 + (l & 3) * 2;
            const float* wr = W1 + (size_t)j * 32;
            uint4 v;
            split2bf(__ldg(&wr[c0]),     __ldg(&wr[c0 + 1]), v.x, v.z);
            split2bf(__ldg(&wr[c0 + 8]), __ldg(&wr[c0 + 9]), v.y, v.w);
            g_W1f[idx] = v;
        }
    }
}

// ---------------- Kernel A: MLP(bf16x3) + GEMM(bf16x3) + epilogue + in-CTA attention ---------
// R10 structure (best): CTA = 128 edges = 8 nodes; 3 CTAs/SM; B via direct __ldg; barrier-free
// main loop. R13 change: chunk loop FULLY UNROLLED -> static plane control flow + cross-chunk
// software pipelining by ptxas.
#define S_KQV  0u              // 16 planes x 128 x 16B = 32768
#define S_TMP  0u              //   tmp 8K aliases planes 0-3 (dead before plane writes)
#define S_EF   0u              //   prologue scratch: 128 x 144B = 18432 (dead before tmp)
#define S_W1F  18432u          //   prologue scratch: 8192 (dead before v-plane writes)
#define S_B1   26624u          //   prologue scratch: 256
#define S_QN   32768u          // 1024
#define S_B2   33792u          // 3072  ..36864
#define S_BAS  36864u          // 4096  ..40960
#define SMEM_SZ (40960u + 1024u)

__global__ void __launch_bounds__(128, 3) k_main(const float* __restrict__ b2,
                                                 const float* __restrict__ basis2,
                                                 const float* __restrict__ basis1,
                                                 const float* __restrict__ f,
                                                 const int* __restrict__ nbr,
                                                 const float* __restrict__ ef,
                                                 const float* __restrict__ b1,
                                                 float* __restrict__ out) {
    extern __shared__ unsigned char smraw[];
    uint32_t base = (smem_u32(smraw) + 1023u) & ~1023u;
    unsigned char* sm = smraw + (base - smem_u32(smraw));
    const float* sB2f = (const float*)(sm + S_B2);
    int tid = threadIdx.x, blk = blockIdx.x;
    int wid = tid >> 5, lane = tid & 31;
    int q = lane & 3;

    // ---- prologue: ef tile + W1 frags + b1 + b2 + basis2 ----
    {
        for (int r = tid; r < 1024; r += 128) {
            int row = r >> 3, seg = r & 7;
            cpa16(base + S_EF + (uint32_t)row * 144u + (uint32_t)seg * 16u,
                  ef + ((size_t)(blk * 128 + row)) * 32 + seg * 4);
        }
        const uint4* wf = (const uint4*)g_W1f;
        for (int r = tid; r < 512; r += 128) cpa16(base + S_W1F + r * 16, wf + r);
        const uint4* g1 = (const uint4*)b1;
        for (int r = tid; r < 16; r += 128) cpa16(base + S_B1 + r * 16, g1 + r);
        const uint4* g2 = (const uint4*)b2;
        for (int r = tid; r < 192; r += 128) cpa16(base + S_B2 + r * 16, g2 + r);
        const uint4* gb = (const uint4*)(basis2 + (size_t)blk * 1024);
        for (int r = tid; r < 256; r += 128) cpa16(base + S_BAS + r * 16, gb + r);
        CP_COMMIT();
    }
    CP_WAIT(0);
    __syncthreads();

    // ---- MLP (bf16x3 tensor): h = relu(ef @ W1^T + b1) -> A frags in-register ----
    uint32_t awh[2][4][4], awl[2][4][4];
    {
        uint32_t efh[2][2][4], efl[2][2][4];
        const float* sEF = (const float*)(sm + S_EF);
#pragma unroll
        for (int mt = 0; mt < 2; mt++)
#pragma unroll
            for (int kt = 0; kt < 2; kt++) {
                int r0 = wid * 32 + mt * 16 + (lane >> 2);
                int c0 = kt * 16 + 2 * q;
                float2 v0 = *(const float2*)&sEF[r0 * 36 + c0];
                float2 v1 = *(const float2*)&sEF[(r0 + 8) * 36 + c0];
                float2 v2 = *(const float2*)&sEF[r0 * 36 + c0 + 8];
                float2 v3 = *(const float2*)&sEF[(r0 + 8) * 36 + c0 + 8];
                split2bf(v0.x, v0.y, efh[mt][kt][0], efl[mt][kt][0]);
                split2bf(v1.x, v1.y, efh[mt][kt][1], efl[mt][kt][1]);
                split2bf(v2.x, v2.y, efh[mt][kt][2], efl[mt][kt][2]);
                split2bf(v3.x, v3.y, efh[mt][kt][3], efl[mt][kt][3]);
            }
        const float* sb1 = (const float*)(sm + S_B1);
#pragma unroll
        for (int nth = 0; nth < 2; nth++) {
            float hc[2][4][4];
#pragma unroll
            for (int mt = 0; mt < 2; mt++)
#pragma unroll
                for (int n4 = 0; n4 < 4; n4++)
#pragma unroll
                    for (int x = 0; x < 4; x++) hc[mt][n4][x] = 0.0f;
#pragma unroll
            for (int kt2 = 0; kt2 < 2; kt2++) {
                uint4 w[4];
#pragma unroll
                for (int n4 = 0; n4 < 4; n4++)
                    w[n4] = *(const uint4*)(sm + S_W1F +
                        (uint32_t)(((kt2 * 8 + nth * 4 + n4) * 32 + lane) * 16));
#pragma unroll
                for (int ps = 0; ps < 3; ps++)
#pragma unroll
                    for (int n4 = 0; n4 < 4; n4++) {
                        const uint32_t* bp = (ps == 1) ? &w[n4].z : &w[n4].x;
#pragma unroll
                        for (int mt = 0; mt < 2; mt++)
                            mma_bf16(hc[mt][n4], (ps == 2) ? efl[mt][kt2] : efh[mt][kt2], bp);
                    }
            }
#pragma unroll
            for (int n4 = 0; n4 < 4; n4++) {
                int nt = nth * 4 + n4;
                float ba = sb1[nt * 8 + 2 * q], bb = sb1[nt * 8 + 2 * q + 1];
                int ktA = nt >> 1, rg = (nt & 1) * 2;
#pragma unroll
                for (int mt = 0; mt < 2; mt++) {
                    float x0 = fmaxf(hc[mt][n4][0] + ba, 0.f);
                    float x1 = fmaxf(hc[mt][n4][1] + bb, 0.f);
                    float x2 = fmaxf(hc[mt][n4][2] + ba, 0.f);
                    float x3 = fmaxf(hc[mt][n4][3] + bb, 0.f);
                    split2bf(x0, x1, awh[mt][ktA][rg],     awl[mt][ktA][rg]);
                    split2bf(x2, x3, awh[mt][ktA][rg + 1], awl[mt][ktA][rg + 1]);
                }
            }
        }
    }
    __syncthreads();           // EF/W1F/B1 scratch dead for all warps

    // ---- tmp: tmp[e, m*2+l] = sum_d f[src,m,d]*basis1[e,d,l] ----
    {
        int e = blk * 128 + tid;
        int src = __ldg(&nbr[e]);
        const float4* fp = (const float4*)(f + (size_t)src * 32);
        float fr[8][4];
#pragma unroll
        for (int m = 0; m < 8; m++) {
            float4 v = __ldg(&fp[m]);
            fr[m][0] = v.x; fr[m][1] = v.y; fr[m][2] = v.z; fr[m][3] = v.w;
        }
        float4 b0 = __ldg((const float4*)(basis1 + (size_t)e * 8));
        float4 b1v = __ldg((const float4*)(basis1 + (size_t)e * 8 + 4));
        float bd[4][2] = {{b0.x, b0.y}, {b0.z, b0.w}, {b1v.x, b1v.y}, {b1v.z, b1v.w}};
        float* dst = (float*)(sm + S_TMP);
#pragma unroll
        for (int m = 0; m < 8; m++)
#pragma unroll
            for (int l = 0; l < 2; l++) {
                float a = fr[m][0] * bd[0][l];
                a = fmaf(fr[m][1], bd[1][l], a);
                a = fmaf(fr[m][2], bd[2][l], a);
                a = fmaf(fr[m][3], bd[3][l], a);
                dst[(m * 2 + l) * 128 + tid] = a;
            }
    }
    __syncthreads();           // tmp visible to all warps

    float tr[4][4];
    {
        const float* sTMPf = (const float*)(sm + S_TMP);
#pragma unroll
        for (int rid = 0; rid < 4; rid++) {
            int row = wid * 32 + (lane >> 2) + rid * 8;
#pragma unroll
            for (int s = 0; s < 4; s++) {
                int i = (s >> 1) * 8 + 2 * q + (s & 1);
                tr[rid][s] = sTMPf[i * 128 + row];
            }
        }
    }
    __syncthreads();           // ALL warps' tr loaded before plane writes clobber tmp bytes

    float acc[2][4][4];
#pragma unroll
    for (int mt = 0; mt < 2; mt++)
#pragma unroll
        for (int n4 = 0; n4 < 4; n4++)
#pragma unroll
            for (int x = 0; x < 4; x++) acc[mt][n4][x] = 0.0f;

    // ==== free-running main loop: FULLY UNROLLED (static plane control flow; ptxas pipelines
    //      B loads of chunk c+1 under epilogue of chunk c) ====
#pragma unroll
    for (int c = 0; c < 12; c++) {
        const uint4* bc = g_Bf + (size_t)c * 1024;
#pragma unroll
        for (int ntg = 0; ntg < 2; ntg++) {
#pragma unroll
            for (int kt = 0; kt < 4; kt++) {
                uint4 b[4];
#pragma unroll
                for (int n4 = 0; n4 < 4; n4++)
                    b[n4] = __ldg(&bc[(size_t)((kt * 8 + ntg * 4 + n4) * 32 + lane)]);
#pragma unroll
                for (int ps = 0; ps < 3; ps++)
#pragma unroll
                    for (int n4 = 0; n4 < 4; n4++) {
                        const uint32_t* bp = (ps == 1) ? &b[n4].z : &b[n4].x;
#pragma unroll
                        for (int mt = 0; mt < 2; mt++)
                            mma_bf16(acc[mt][n4], (ps == 2) ? awl[mt][kt] : awh[mt][kt], bp);
                    }
            }

            // ---- fragment-direct epilogue (half -> one complete plane) ----
            float p[4][2];
#pragma unroll
            for (int rid = 0; rid < 4; rid++) { p[rid][0] = 0.f; p[rid][1] = 0.f; }
#pragma unroll
            for (int mt = 0; mt < 2; mt++)
#pragma unroll
                for (int n4 = 0; n4 < 4; n4++) {
                    int o2 = n4 >> 1, s0 = (n4 & 1) * 2;
                    float2 bb = *(const float2*)&sB2f[c * 64 + (ntg * 4 + n4) * 8 + q * 2];
#pragma unroll
                    for (int h = 0; h < 2; h++) {
                        int rid = mt * 2 + h;
                        p[rid][o2] = fmaf(acc[mt][n4][h * 2] + bb.x, tr[rid][s0],
                                     fmaf(acc[mt][n4][h * 2 + 1] + bb.y, tr[rid][s0 + 1],
                                          p[rid][o2]));
                        acc[mt][n4][h * 2] = 0.0f;
                        acc[mt][n4][h * 2 + 1] = 0.0f;
                    }
                }
#pragma unroll
            for (int rid = 0; rid < 4; rid++)
#pragma unroll
                for (int o2 = 0; o2 < 2; o2++) {
                    p[rid][o2] += __shfl_xor_sync(0xffffffffu, p[rid][o2], 1);
                    p[rid][o2] += __shfl_xor_sync(0xffffffffu, p[rid][o2], 2);
                }

            if (c < 4 || c >= 8) {
                if (q == 0) {
                    int plane = ((c < 4) ? (c * 2) : ((c - 8) * 2 + 8)) + ntg;
#pragma unroll
                    for (int rid = 0; rid < 4; rid++) {
                        int el = wid * 32 + (lane >> 2) + rid * 8;
                        float4 p0 = *(const float4*)(sm + S_BAS + el * 32);
                        float4 p1 = *(const float4*)(sm + S_BAS + el * 32 + 16);
                        float a0 = p[rid][0], a1 = p[rid][1];
                        float4 o4;
                        o4.x = fmaf(a0, p0.x, a1 * p1.x);
                        o4.y = fmaf(a0, p0.y, a1 * p1.y);
                        o4.z = fmaf(a0, p0.z, a1 * p1.z);
                        o4.w = fmaf(a0, p0.w, a1 * p1.w);
                        *(float4*)(sm + S_KQV + (size_t)plane * 2048 + el * 16) = o4;
                    }
                }
            } else {
                int qp = (c - 4) * 2 + ntg;
                float4 an[2];
                an[0] = make_float4(0.f, 0.f, 0.f, 0.f);
                an[1] = make_float4(0.f, 0.f, 0.f, 0.f);
#pragma unroll
                for (int rid = 0; rid < 4; rid++) {
                    int el = wid * 32 + (lane >> 2) + rid * 8;
                    float4 p0 = *(const float4*)(sm + S_BAS + el * 32);
                    float4 p1 = *(const float4*)(sm + S_BAS + el * 32 + 16);
                    int nn = rid >> 1;
                    float a0 = p[rid][0], a1 = p[rid][1];
                    an[nn].x = fmaf(a0, p0.x, fmaf(a1, p1.x, an[nn].x));
                    an[nn].y = fmaf(a0, p0.y, fmaf(a1, p1.y, an[nn].y));
                    an[nn].z = fmaf(a0, p0.z, fmaf(a1, p1.z, an[nn].z));
                    an[nn].w = fmaf(a0, p0.w, fmaf(a1, p1.w, an[nn].w));
                }
#pragma unroll
                for (int nn = 0; nn < 2; nn++)
#pragma unroll
                    for (int d = 4; d <= 16; d <<= 1) {
                        an[nn].x += __shfl_xor_sync(0xffffffffu, an[nn].x, d);
                        an[nn].y += __shfl_xor_sync(0xffffffffu, an[nn].y, d);
                        an[nn].z += __shfl_xor_sync(0xffffffffu, an[nn].z, d);
                        an[nn].w += __shfl_xor_sync(0xffffffffu, an[nn].w, d);
                    }
                if (lane == 0) {
                    *(float4*)(sm + S_QN + (size_t)((wid * 2 + 0) * 8 + qp) * 16) = an[0];
                    *(float4*)(sm + S_QN + (size_t)((wid * 2 + 1) * 8 + qp) * 16) = an[1];
                }
            }
        }
    }

    // ---- in-CTA attention: 8 nodes, 16 lanes per node ----
    __syncthreads();
    {
        int k16 = lane & 15, nh = lane >> 4;
        int nl = wid * 2 + nh;
        int n = blk * 8 + nl;
        int el = nl * 16 + k16;
        float s[4] = {0.f, 0.f, 0.f, 0.f};
#pragma unroll
        for (int pp = 0; pp < 8; pp++) {
            float4 kv = *(const float4*)(sm + S_KQV + (size_t)pp * 2048 + el * 16);
            float4 qv = *(const float4*)(sm + S_QN + (size_t)(nl * 8 + pp) * 16);
            s[pp >> 1] = fmaf(kv.x, qv.x, fmaf(kv.y, qv.y,
                         fmaf(kv.z, qv.z, fmaf(kv.w, qv.w, s[pp >> 1]))));
        }
        const float scale = 0.35355339059327373f * 0.0625f;  // 8^-0.5 * 1/16 (q mean)
#pragma unroll
        for (int h = 0; h < 4; h++) {
            s[h] *= scale;
            float m = s[h];
#pragma unroll
            for (int d = 1; d < 16; d <<= 1)
                m = fmaxf(m, __shfl_xor_sync(0xffffffffu, m, d));
            float w = __expf(s[h] - m);
            float z = w;
#pragma unroll
            for (int d = 1; d < 16; d <<= 1)
                z += __shfl_xor_sync(0xffffffffu, z, d);
            s[h] = w / z;
        }
#pragma unroll
        for (int pp = 0; pp < 8; pp++) {
            float4 vv = *(const float4*)(sm + S_KQV + (size_t)(8 + pp) * 2048 + el * 16);
            float w = s[pp >> 1];
            float4 o4 = make_float4(w * vv.x, w * vv.y, w * vv.z, w * vv.w);
#pragma unroll
            for (int d = 1; d < 16; d <<= 1) {
                o4.x += __shfl_xor_sync(0xffffffffu, o4.x, d);
                o4.y += __shfl_xor_sync(0xffffffffu, o4.y, d);
                o4.z += __shfl_xor_sync(0xffffffffu, o4.z, d);
                o4.w += __shfl_xor_sync(0xffffffffu, o4.w, d);
            }
            if (k16 == 0)
                *(float4*)(out + (size_t)n * 32 + pp * 4) = o4;
        }
    }
}

extern "C" void kernel_launch(void* const* d_in, const int* in_sizes, int n_in,
                              void* d_out, int out_size) {
    const float* basis1 = (const float*)d_in[0];
    const float* basis2 = (const float*)d_in[1];
    const float* ef     = (const float*)d_in[2];
    const float* f      = (const float*)d_in[3];
    const float* W1     = (const float*)d_in[4];
    const float* b1     = (const float*)d_in[5];
    const float* W2     = (const float*)d_in[6];
    const float* b2     = (const float*)d_in[7];
    const int*   nbr    = (const int*)d_in[8];
    float* out = (float*)d_out;

    cudaFuncSetAttribute(k_main, cudaFuncAttributeMaxDynamicSharedMemorySize, SMEM_SZ);

    k_prep<<<13, 128>>>(W2, W1);
    k_main<<<EN / 128, 128, SMEM_SZ>>>(b2, basis2, basis1, f, nbr, ef, b1, out);
}

// round 14
// speedup vs baseline: 1.0781x; 1.0326x over previous
#include <cuda_runtime.h>
#include <cuda_bf16.h>
#include <cstdint>

#define EN 160000      // edges = N*K
#define NN 10000       // nodes

// ---------------- static device scratch -----------------------------------------------------
__device__ __align__(16) uint4 g_Bf[12 * 1024];   // W2 bf16 packed {hi0,hi1,lo0,lo1} [chunk][kt][nt][lane]
__device__ __align__(16) uint4 g_W1f[512];        // W1 bf16 packed [kt2(2)][nt(8)][lane]

// ---------------- helpers --------------------------------------------------------------------
__device__ __forceinline__ uint32_t smem_u32(const void* p) {
    uint32_t a;
    asm("{ .reg .u64 t; cvta.to.shared.u64 t, %1; cvt.u32.u64 %0, t; }" : "=r"(a) : "l"(p));
    return a;
}
__device__ __forceinline__ void mma_bf16(float* c, const uint32_t* a, const uint32_t* b) {
    asm volatile("mma.sync.aligned.m16n8k16.row.col.f32.bf16.bf16.f32 "
        "{%0,%1,%2,%3}, {%4,%5,%6,%7}, {%8,%9}, {%0,%1,%2,%3};"
        : "+f"(c[0]), "+f"(c[1]), "+f"(c[2]), "+f"(c[3])
        : "r"(a[0]), "r"(a[1]), "r"(a[2]), "r"(a[3]), "r"(b[0]), "r"(b[1]));
}
__device__ __forceinline__ void cpa16(uint32_t dst, const void* src) {
    asm volatile("cp.async.cg.shared.global [%0], [%1], 16;" :: "r"(dst), "l"(src));
}
#define CP_COMMIT() asm volatile("cp.async.commit_group;" ::: "memory")
#define CP_WAIT(n)  asm volatile("cp.async.wait_group %0;" :: "n"(n) : "memory")

__device__ __forceinline__ void split2bf(float a, float b, uint32_t& h, uint32_t& l) {
    __nv_bfloat16 ah = __float2bfloat16(a), bh = __float2bfloat16(b);
    __nv_bfloat16 al = __float2bfloat16(a - __bfloat162float(ah));
    __nv_bfloat16 bl = __float2bfloat16(b - __bfloat162float(bh));
    h = (uint32_t)__bfloat16_as_ushort(ah) | ((uint32_t)__bfloat16_as_ushort(bh) << 16);
    l = (uint32_t)__bfloat16_as_ushort(al) | ((uint32_t)__bfloat16_as_ushort(bl) << 16);
}

// ---------------- Kernel P: pack W2 (12 blocks) and W1 (block 12), bf16 hi/lo ----------------
__global__ void k_prep(const float* __restrict__ W2, const float* __restrict__ W1) {
    int bid = blockIdx.x, tid = threadIdx.x;
    if (bid < 12) {
        int c = bid;
        for (int idx = tid; idx < 1024; idx += 128) {
            int kt = idx >> 8, nt = (idx >> 5) & 7, l = idx & 31;
            int row = c * 64 + nt * 8 + (l >> 2);
            int j0 = kt * 16 + (l & 3) * 2;
            const float* wr = W2 + (size_t)row * 64;
            uint4 v;
            split2bf(__ldg(&wr[j0]),     __ldg(&wr[j0 + 1]), v.x, v.z);
            split2bf(__ldg(&wr[j0 + 8]), __ldg(&wr[j0 + 9]), v.y, v.w);
            g_Bf[c * 1024 + idx] = v;
        }
    } else {
        for (int idx = tid; idx < 512; idx += 128) {
            int kt = idx >> 8, nt = (idx >> 5) & 7, l = idx & 31;
            int j = nt * 8 + (l >> 2);
            int c0 = kt * 16 + (l & 3) * 2;
            const float* wr = W1 + (size_t)j * 32;
            uint4 v;
            split2bf(__ldg(&wr[c0]),     __ldg(&wr[c0 + 1]), v.x, v.z);
            split2bf(__ldg(&wr[c0 + 8]), __ldg(&wr[c0 + 9]), v.y, v.w);
            g_W1f[idx] = v;
        }
    }
}

// ---------------- Kernel A: MLP(bf16x3) + GEMM(bf16x3) + UNIFORM epilogue + attention --------
// R10 structure (3 CTAs/SM, B via __ldg, barrier-free loop) with a branch-free epilogue:
// ALL 24 m2-planes (k 0-7, q 8-15, v 16-23) stored to smem; per-node q-mean deferred to the
// attention phase (single 16-lane xor-reduce per plane).
#define S_KQV  0u              // 24 planes x 128 x 16B = 49152
#define S_TMP  0u              //   tmp 8K aliases planes 0-3 (k planes; guarded by tr-sync)
#define S_EF   0u              //   prologue scratch: 128 x 144B = 18432 (dead before tmp)
#define S_W1F  18432u          //   prologue scratch: 8192 (dead before plane 9+ writes)
#define S_B1   26624u          //   prologue scratch: 256
#define S_B2   49152u          // 3072  ..52224
#define S_BAS  52224u          // 4096  ..56320
#define SMEM_SZ (56320u + 1024u)

__global__ void __launch_bounds__(128, 3) k_main(const float* __restrict__ b2,
                                                 const float* __restrict__ basis2,
                                                 const float* __restrict__ basis1,
                                                 const float* __restrict__ f,
                                                 const int* __restrict__ nbr,
                                                 const float* __restrict__ ef,
                                                 const float* __restrict__ b1,
                                                 float* __restrict__ out) {
    extern __shared__ unsigned char smraw[];
    uint32_t base = (smem_u32(smraw) + 1023u) & ~1023u;
    unsigned char* sm = smraw + (base - smem_u32(smraw));
    const float* sB2f = (const float*)(sm + S_B2);
    int tid = threadIdx.x, blk = blockIdx.x;
    int wid = tid >> 5, lane = tid & 31;
    int q = lane & 3;

    // ---- prologue: ef tile + W1 frags + b1 + b2 + basis2 ----
    {
        for (int r = tid; r < 1024; r += 128) {
            int row = r >> 3, seg = r & 7;
            cpa16(base + S_EF + (uint32_t)row * 144u + (uint32_t)seg * 16u,
                  ef + ((size_t)(blk * 128 + row)) * 32 + seg * 4);
        }
        const uint4* wf = (const uint4*)g_W1f;
        for (int r = tid; r < 512; r += 128) cpa16(base + S_W1F + r * 16, wf + r);
        const uint4* g1 = (const uint4*)b1;
        for (int r = tid; r < 16; r += 128) cpa16(base + S_B1 + r * 16, g1 + r);
        const uint4* g2 = (const uint4*)b2;
        for (int r = tid; r < 192; r += 128) cpa16(base + S_B2 + r * 16, g2 + r);
        const uint4* gb = (const uint4*)(basis2 + (size_t)blk * 1024);
        for (int r = tid; r < 256; r += 128) cpa16(base + S_BAS + r * 16, gb + r);
        CP_COMMIT();
    }
    CP_WAIT(0);
    __syncthreads();

    // ---- MLP (bf16x3 tensor): h = relu(ef @ W1^T + b1) -> A frags in-register ----
    uint32_t awh[2][4][4], awl[2][4][4];
    {
        uint32_t efh[2][2][4], efl[2][2][4];
        const float* sEF = (const float*)(sm + S_EF);
#pragma unroll
        for (int mt = 0; mt < 2; mt++)
#pragma unroll
            for (int kt = 0; kt < 2; kt++) {
                int r0 = wid * 32 + mt * 16 + (lane >> 2);
                int c0 = kt * 16 + 2 * q;
                float2 v0 = *(const float2*)&sEF[r0 * 36 + c0];
                float2 v1 = *(const float2*)&sEF[(r0 + 8) * 36 + c0];
                float2 v2 = *(const float2*)&sEF[r0 * 36 + c0 + 8];
                float2 v3 = *(const float2*)&sEF[(r0 + 8) * 36 + c0 + 8];
                split2bf(v0.x, v0.y, efh[mt][kt][0], efl[mt][kt][0]);
                split2bf(v1.x, v1.y, efh[mt][kt][1], efl[mt][kt][1]);
                split2bf(v2.x, v2.y, efh[mt][kt][2], efl[mt][kt][2]);
                split2bf(v3.x, v3.y, efh[mt][kt][3], efl[mt][kt][3]);
            }
        const float* sb1 = (const float*)(sm + S_B1);
#pragma unroll
        for (int nth = 0; nth < 2; nth++) {
            float hc[2][4][4];
#pragma unroll
            for (int mt = 0; mt < 2; mt++)
#pragma unroll
                for (int n4 = 0; n4 < 4; n4++)
#pragma unroll
                    for (int x = 0; x < 4; x++) hc[mt][n4][x] = 0.0f;
#pragma unroll
            for (int kt2 = 0; kt2 < 2; kt2++) {
                uint4 w[4];
#pragma unroll
                for (int n4 = 0; n4 < 4; n4++)
                    w[n4] = *(const uint4*)(sm + S_W1F +
                        (uint32_t)(((kt2 * 8 + nth * 4 + n4) * 32 + lane) * 16));
#pragma unroll
                for (int ps = 0; ps < 3; ps++)
#pragma unroll
                    for (int n4 = 0; n4 < 4; n4++) {
                        const uint32_t* bp = (ps == 1) ? &w[n4].z : &w[n4].x;
#pragma unroll
                        for (int mt = 0; mt < 2; mt++)
                            mma_bf16(hc[mt][n4], (ps == 2) ? efl[mt][kt2] : efh[mt][kt2], bp);
                    }
            }
#pragma unroll
            for (int n4 = 0; n4 < 4; n4++) {
                int nt = nth * 4 + n4;
                float ba = sb1[nt * 8 + 2 * q], bb = sb1[nt * 8 + 2 * q + 1];
                int ktA = nt >> 1, rg = (nt & 1) * 2;
#pragma unroll
                for (int mt = 0; mt < 2; mt++) {
                    float x0 = fmaxf(hc[mt][n4][0] + ba, 0.f);
                    float x1 = fmaxf(hc[mt][n4][1] + bb, 0.f);
                    float x2 = fmaxf(hc[mt][n4][2] + ba, 0.f);
                    float x3 = fmaxf(hc[mt][n4][3] + bb, 0.f);
                    split2bf(x0, x1, awh[mt][ktA][rg],     awl[mt][ktA][rg]);
                    split2bf(x2, x3, awh[mt][ktA][rg + 1], awl[mt][ktA][rg + 1]);
                }
            }
        }
    }
    __syncthreads();           // EF/W1F/B1 scratch dead for all warps

    // ---- tmp: tmp[e, m*2+l] = sum_d f[src,m,d]*basis1[e,d,l] ----
    {
        int e = blk * 128 + tid;
        int src = __ldg(&nbr[e]);
        const float4* fp = (const float4*)(f + (size_t)src * 32);
        float fr[8][4];
#pragma unroll
        for (int m = 0; m < 8; m++) {
            float4 v = __ldg(&fp[m]);
            fr[m][0] = v.x; fr[m][1] = v.y; fr[m][2] = v.z; fr[m][3] = v.w;
        }
        float4 b0 = __ldg((const float4*)(basis1 + (size_t)e * 8));
        float4 b1v = __ldg((const float4*)(basis1 + (size_t)e * 8 + 4));
        float bd[4][2] = {{b0.x, b0.y}, {b0.z, b0.w}, {b1v.x, b1v.y}, {b1v.z, b1v.w}};
        float* dst = (float*)(sm + S_TMP);
#pragma unroll
        for (int m = 0; m < 8; m++)
#pragma unroll
            for (int l = 0; l < 2; l++) {
                float a = fr[m][0] * bd[0][l];
                a = fmaf(fr[m][1], bd[1][l], a);
                a = fmaf(fr[m][2], bd[2][l], a);
                a = fmaf(fr[m][3], bd[3][l], a);
                dst[(m * 2 + l) * 128 + tid] = a;
            }
    }
    __syncthreads();           // tmp visible to all warps

    float tr[4][4];
    {
        const float* sTMPf = (const float*)(sm + S_TMP);
#pragma unroll
        for (int rid = 0; rid < 4; rid++) {
            int row = wid * 32 + (lane >> 2) + rid * 8;
#pragma unroll
            for (int s = 0; s < 4; s++) {
                int i = (s >> 1) * 8 + 2 * q + (s & 1);
                tr[rid][s] = sTMPf[i * 128 + row];
            }
        }
    }
    __syncthreads();           // ALL warps' tr loaded before plane writes clobber tmp bytes

    float acc[2][4][4];
#pragma unroll
    for (int mt = 0; mt < 2; mt++)
#pragma unroll
        for (int n4 = 0; n4 < 4; n4++)
#pragma unroll
            for (int x = 0; x < 4; x++) acc[mt][n4][x] = 0.0f;

    // ==== free-running main loop: UNIFORM epilogue, plane = c*2+ntg, no branches, no barriers ====
    for (int c = 0; c < 12; c++) {
        const uint4* bc = g_Bf + (size_t)c * 1024;
#pragma unroll
        for (int ntg = 0; ntg < 2; ntg++) {
#pragma unroll
            for (int kt = 0; kt < 4; kt++) {
                uint4 b[4];
#pragma unroll
                for (int n4 = 0; n4 < 4; n4++)
                    b[n4] = __ldg(&bc[(size_t)((kt * 8 + ntg * 4 + n4) * 32 + lane)]);
#pragma unroll
                for (int ps = 0; ps < 3; ps++)
#pragma unroll
                    for (int n4 = 0; n4 < 4; n4++) {
                        const uint32_t* bp = (ps == 1) ? &b[n4].z : &b[n4].x;
#pragma unroll
                        for (int mt = 0; mt < 2; mt++)
                            mma_bf16(acc[mt][n4], (ps == 2) ? awl[mt][kt] : awh[mt][kt], bp);
                    }
            }

            // ---- fragment-direct epilogue (half -> one complete plane, ALWAYS stored) ----
            float p[4][2];
#pragma unroll
            for (int rid = 0; rid < 4; rid++) { p[rid][0] = 0.f; p[rid][1] = 0.f; }
#pragma unroll
            for (int mt = 0; mt < 2; mt++)
#pragma unroll
                for (int n4 = 0; n4 < 4; n4++) {
                    int o2 = n4 >> 1, s0 = (n4 & 1) * 2;
                    float2 bb = *(const float2*)&sB2f[c * 64 + (ntg * 4 + n4) * 8 + q * 2];
#pragma unroll
                    for (int h = 0; h < 2; h++) {
                        int rid = mt * 2 + h;
                        p[rid][o2] = fmaf(acc[mt][n4][h * 2] + bb.x, tr[rid][s0],
                                     fmaf(acc[mt][n4][h * 2 + 1] + bb.y, tr[rid][s0 + 1],
                                          p[rid][o2]));
                        acc[mt][n4][h * 2] = 0.0f;
                        acc[mt][n4][h * 2 + 1] = 0.0f;
                    }
                }
#pragma unroll
            for (int rid = 0; rid < 4; rid++)
#pragma unroll
                for (int o2 = 0; o2 < 2; o2++) {
                    p[rid][o2] += __shfl_xor_sync(0xffffffffu, p[rid][o2], 1);
                    p[rid][o2] += __shfl_xor_sync(0xffffffffu, p[rid][o2], 2);
                }

            if (q == 0) {
                int plane = c * 2 + ntg;      // k: 0-7, q: 8-15, v: 16-23
#pragma unroll
                for (int rid = 0; rid < 4; rid++) {
                    int el = wid * 32 + (lane >> 2) + rid * 8;
                    float4 p0 = *(const float4*)(sm + S_BAS + el * 32);
                    float4 p1 = *(const float4*)(sm + S_BAS + el * 32 + 16);
                    float a0 = p[rid][0], a1 = p[rid][1];
                    float4 o4;
                    o4.x = fmaf(a0, p0.x, a1 * p1.x);
                    o4.y = fmaf(a0, p0.y, a1 * p1.y);
                    o4.z = fmaf(a0, p0.z, a1 * p1.z);
                    o4.w = fmaf(a0, p0.w, a1 * p1.w);
                    *(float4*)(sm + S_KQV + (size_t)plane * 2048 + el * 16) = o4;
                }
            }
        }
    }

    // ---- in-CTA attention: 8 nodes, 16 lanes per node; q-mean via 16-lane xor-reduce ----
    __syncthreads();
    {
        int k16 = lane & 15, nh = lane >> 4;
        int nl = wid * 2 + nh;
        int n = blk * 8 + nl;
        int el = nl * 16 + k16;
        float s[4] = {0.f, 0.f, 0.f, 0.f};
#pragma unroll
        for (int pp = 0; pp < 8; pp++) {
            float4 qv = *(const float4*)(sm + S_KQV + (size_t)(8 + pp) * 2048 + el * 16);
#pragma unroll
            for (int d = 1; d < 16; d <<= 1) {
                qv.x += __shfl_xor_sync(0xffffffffu, qv.x, d);
                qv.y += __shfl_xor_sync(0xffffffffu, qv.y, d);
                qv.z += __shfl_xor_sync(0xffffffffu, qv.z, d);
                qv.w += __shfl_xor_sync(0xffffffffu, qv.w, d);
            }
            float4 kv = *(const float4*)(sm + S_KQV + (size_t)pp * 2048 + el * 16);
            s[pp >> 1] = fmaf(kv.x, qv.x, fmaf(kv.y, qv.y,
                         fmaf(kv.z, qv.z, fmaf(kv.w, qv.w, s[pp >> 1]))));
        }
        const float scale = 0.35355339059327373f * 0.0625f;  // 8^-0.5 * 1/16 (q mean)
#pragma unroll
        for (int h = 0; h < 4; h++) {
            s[h] *= scale;
            float m = s[h];
#pragma unroll
            for (int d = 1; d < 16; d <<= 1)
                m = fmaxf(m, __shfl_xor_sync(0xffffffffu, m, d));
            float w = __expf(s[h] - m);
            float z = w;
#pragma unroll
            for (int d = 1; d < 16; d <<= 1)
                z += __shfl_xor_sync(0xffffffffu, z, d);
            s[h] = w / z;
        }
#pragma unroll
        for (int pp = 0; pp < 8; pp++) {
            float4 vv = *(const float4*)(sm + S_KQV + (size_t)(16 + pp) * 2048 + el * 16);
            float w = s[pp >> 1];
            float4 o4 = make_float4(w * vv.x, w * vv.y, w * vv.z, w * vv.w);
#pragma unroll
            for (int d = 1; d < 16; d <<= 1) {
                o4.x += __shfl_xor_sync(0xffffffffu, o4.x, d);
                o4.y += __shfl_xor_sync(0xffffffffu, o4.y, d);
                o4.z += __shfl_xor_sync(0xffffffffu, o4.z, d);
                o4.w += __shfl_xor_sync(0xffffffffu, o4.w, d);
            }
            if (k16 == 0)
                *(float4*)(out + (size_t)n * 32 + pp * 4) = o4;
        }
    }
}

extern "C" void kernel_launch(void* const* d_in, const int* in_sizes, int n_in,
                              void* d_out, int out_size) {
    const float* basis1 = (const float*)d_in[0];
    const float* basis2 = (const float*)d_in[1];
    const float* ef     = (const float*)d_in[2];
    const float* f      = (const float*)d_in[3];
    const float* W1     = (const float*)d_in[4];
    const float* b1     = (const float*)d_in[5];
    const float* W2     = (const float*)d_in[6];
    const float* b2     = (const float*)d_in[7];
    const int*   nbr    = (const int*)d_in[8];
    float* out = (float*)d_out;

    cudaFuncSetAttribute(k_main, cudaFuncAttributeMaxDynamicSharedMemorySize, SMEM_SZ);

    k_prep<<<13, 128>>>(W2, W1);
    k_main<<<EN / 128, 128, SMEM_SZ>>>(b2, basis2, basis1, f, nbr, ef, b1, out);
}